// round 16
// baseline (speedup 1.0000x reference)
#include <cuda_runtime.h>
#include <cuda_bf16.h>

#define B    128
#define N1   32
#define N2   32
#define D1   23
#define D2   13
#define NN   64
#define E    72
#define H    256
#define F    128
#define LNCNT 4608

typedef unsigned long long u64;

// ---- f32x2 packed helpers (sm_103a) ----
__device__ __forceinline__ u64 pk(float lo, float hi) {
    u64 r; asm("mov.b64 %0, {%1,%2};" : "=l"(r) : "f"(lo), "f"(hi)); return r;
}
__device__ __forceinline__ void upk(u64 x, float& lo, float& hi) {
    asm("mov.b64 {%0,%1}, %2;" : "=f"(lo), "=f"(hi) : "l"(x));
}
__device__ __forceinline__ u64 add2(u64 a, u64 b) {
    u64 d; asm("add.rn.f32x2 %0,%1,%2;" : "=l"(d) : "l"(a), "l"(b)); return d;
}
__device__ __forceinline__ u64 mul2(u64 a, u64 b) {
    u64 d; asm("mul.rn.f32x2 %0,%1,%2;" : "=l"(d) : "l"(a), "l"(b)); return d;
}
__device__ __forceinline__ u64 fma2(u64 a, u64 b, u64 c) {
    u64 d; asm("fma.rn.f32x2 %0,%1,%2,%3;" : "=l"(d) : "l"(a), "l"(b), "l"(c)); return d;
}
__device__ __forceinline__ u64 shfl_xor_u64(u64 x, int o) {
    float lo, hi; upk(x, lo, hi);
    lo = __shfl_xor_sync(~0u, lo, o);
    hi = __shfl_xor_sync(~0u, hi, o);
    return pk(lo, hi);
}

// Fused packed ELU: e = min(max(t,0), e^t - 1), t = u + v.
__device__ __forceinline__ u64 elu2(u64 u2, u64 v2, u64 l2e, u64 neg1) {
    u64 e;
    asm("{\n\t"
        ".reg .b64 t2, x2, em2;\n\t"
        ".reg .f32 t0, t1, x0, x1, m0, m1, r0, r1;\n\t"
        "add.rn.f32x2 t2, %1, %2;\n\t"
        "mul.rn.f32x2 x2, t2, %3;\n\t"
        "mov.b64 {x0,x1}, x2;\n\t"
        "ex2.approx.ftz.f32 x0, x0;\n\t"
        "ex2.approx.ftz.f32 x1, x1;\n\t"
        "mov.b64 x2, {x0,x1};\n\t"
        "add.rn.f32x2 em2, x2, %4;\n\t"
        "mov.b64 {m0,m1}, em2;\n\t"
        "mov.b64 {t0,t1}, t2;\n\t"
        "max.f32 r0, t0, 0f00000000;\n\t"
        "max.f32 r1, t1, 0f00000000;\n\t"
        "min.f32 r0, r0, m0;\n\t"
        "min.f32 r1, r1, m1;\n\t"
        "mov.b64 %0, {r0,r1};\n\t"
        "}" : "=l"(e) : "l"(u2), "l"(v2), "l"(l2e), "l"(neg1));
    return e;
}

// Scratch
__device__ float g_a[B * NN * E];
__device__ float g_u[B * NN * H];
__device__ float g_v[B * NN * H];
__device__ float g_p[B * 4 * H];
__device__ int   g_cnt[B];          // zero-init; finisher resets (replay-safe)

// ---------------------------------------------------------------------------
// K1: split-embedding + joint LayerNorm. One block per b, weights in smem.
// ---------------------------------------------------------------------------
__global__ __launch_bounds__(256) void k_embed_ln(
    const float* __restrict__ xa, const float* __restrict__ xb,
    const float* __restrict__ Wa, const float* __restrict__ ba,
    const float* __restrict__ Wb, const float* __restrict__ bb,
    const float* __restrict__ g0, const float* __restrict__ b0)
{
    const int b   = blockIdx.x;
    const int tid = threadIdx.x;
    __shared__ float sWa[D1 * E];
    __shared__ float sWb[D2 * E];
    __shared__ float sba[E], sbb[E];
    __shared__ float rsum[8], rssq[8];
    __shared__ float s_mean, s_rstd;

    for (int i = tid; i < D1 * E; i += 256) sWa[i] = Wa[i];
    for (int i = tid; i < D2 * E; i += 256) sWb[i] = Wb[i];
    if (tid < E) { sba[tid] = ba[tid]; sbb[tid] = bb[tid]; }
    __syncthreads();

    float vals[18];
    float sum = 0.f, ssq = 0.f;

    #pragma unroll
    for (int c = 0; c < 18; ++c) {
        const int idx = tid + c * 256;
        const int n = idx / E;
        const int e = idx - n * E;
        float acc;
        if (n < N1) {
            acc = sba[e];
            const float* xr = xa + (b * N1 + n) * D1;
            #pragma unroll
            for (int k = 0; k < D1; ++k) acc = fmaf(xr[k], sWa[k * E + e], acc);
        } else {
            acc = sbb[e];
            const float* xr = xb + (b * N2 + (n - N1)) * D2;
            #pragma unroll
            for (int k = 0; k < D2; ++k) acc = fmaf(xr[k], sWb[k * E + e], acc);
        }
        vals[c] = acc;
        sum += acc;
        ssq = fmaf(acc, acc, ssq);
    }

    #pragma unroll
    for (int o = 16; o; o >>= 1) {
        sum += __shfl_xor_sync(~0u, sum, o);
        ssq += __shfl_xor_sync(~0u, ssq, o);
    }
    const int w = tid >> 5, lane = tid & 31;
    if (lane == 0) { rsum[w] = sum; rssq[w] = ssq; }
    __syncthreads();
    if (tid == 0) {
        float s = 0.f, q = 0.f;
        #pragma unroll
        for (int i = 0; i < 8; ++i) { s += rsum[i]; q += rssq[i]; }
        const float mean = s * (1.f / LNCNT);
        const float var  = fmaf(q, 1.f / LNCNT, -mean * mean);
        s_mean = mean;
        s_rstd = rsqrtf(var + 1e-5f);
    }
    __syncthreads();
    const float mean = s_mean, rstd = s_rstd;

    #pragma unroll
    for (int c = 0; c < 18; ++c) {
        const int idx = tid + c * 256;
        g_a[b * LNCNT + idx] = (vals[c] - mean) * rstd * g0[idx] + b0[idx];
    }
}

// ---------------------------------------------------------------------------
// K2: u = a @ Wg[0:72] + b_g ; v = a @ Wg[72:144].
// 32 rows/block (grid 256): Wg L2 traffic halved vs 16-row version.
// ---------------------------------------------------------------------------
__global__ __launch_bounds__(256) void k_uv(
    const float* __restrict__ Wg, const float* __restrict__ bg)
{
    __shared__ float sa[E * 32];
    const int m0 = blockIdx.x * 32;
    const int h  = threadIdx.x;

    for (int idx = h; idx < E * 32; idx += 256) {
        const int rr = idx / E, k = idx - rr * E;
        sa[k * 32 + rr] = g_a[(m0 + rr) * E + k];
    }
    __syncthreads();

    const float bgh = bg[h];
    u64 uacc[16], vacc[16];
    const u64 bg2 = pk(bgh, bgh);
    #pragma unroll
    for (int p = 0; p < 16; ++p) { uacc[p] = bg2; vacc[p] = 0ull; }

    #pragma unroll 4
    for (int k = 0; k < E; ++k) {
        const ulonglong2* ar = (const ulonglong2*)&sa[k * 32];
        u64 av[16];
        #pragma unroll
        for (int q = 0; q < 8; ++q) {
            const ulonglong2 t = ar[q];
            av[2 * q] = t.x; av[2 * q + 1] = t.y;
        }
        const float w0 = Wg[k * H + h];
        const float w1 = Wg[(E + k) * H + h];
        const u64 w02 = pk(w0, w0);
        const u64 w12 = pk(w1, w1);
        #pragma unroll
        for (int p = 0; p < 16; ++p) {
            uacc[p] = fma2(av[p], w02, uacc[p]);
            vacc[p] = fma2(av[p], w12, vacc[p]);
        }
    }

    #pragma unroll
    for (int p = 0; p < 16; ++p) {
        float lo, hi;
        upk(uacc[p], lo, hi);
        g_u[(m0 + 2 * p) * H + h]     = lo;
        g_u[(m0 + 2 * p + 1) * H + h] = hi;
        upk(vacc[p], lo, hi);
        g_v[(m0 + 2 * p) * H + h]     = lo;
        g_v[(m0 + 2 * p + 1) * H + h] = hi;
    }
}

// ---------------------------------------------------------------------------
// K3: pairwise Σ_j LN_H(ELU(u_i + v_j)) + FUSED FINALE.
// 512-thr block = (b, iq): 16 i's share one v[b] staging; R5-verbatim loop.
// Last block per b (atomic counter) runs the final reduce + W_f GEMM inline,
// overlapping it with other b's pair work. Grid = 512.
// ---------------------------------------------------------------------------
__global__ __launch_bounds__(512) void k_pair(
    const float* __restrict__ lg, const float* __restrict__ lb,
    const float* __restrict__ Wf, const float* __restrict__ bf,
    float* __restrict__ out)
{
    extern __shared__ float sv[];               // [64][256] swizzled v[b]; reused
    __shared__ int s_flag;
    const int bid  = blockIdx.x;
    const int b    = bid >> 2;
    const int iq   = bid & 3;
    const int tid  = threadIdx.x;
    const int w    = tid >> 5;                  // 0..15
    const int lane = tid & 31;
    const int half = lane >> 4;
    const int sub  = lane & 15;
    const int ch0  = sub * 16;

    {
        const float4* vb = (const float4*)(g_v + b * NN * H);
        float4* s4 = (float4*)sv;
        #pragma unroll
        for (int c = 0; c < 8; ++c) {
            const int g = tid + c * 512;        // < 4096
            const int j = g >> 6;
            const int q = g & 63;
            s4[j * 64 + (q & 3) * 16 + (q >> 2)] = vb[g];
        }
    }

    const int m = b * NN + iq * 16 + w;

    u64 ru2[8];
    {
        const ulonglong2* uu = (const ulonglong2*)(g_u + m * H + ch0);
        const ulonglong2 a0 = uu[0], a1 = uu[1], a2 = uu[2], a3 = uu[3];
        ru2[0] = a0.x; ru2[1] = a0.y; ru2[2] = a1.x; ru2[3] = a1.y;
        ru2[4] = a2.x; ru2[5] = a2.y; ru2[6] = a3.x; ru2[7] = a3.y;
    }
    u64 acc2[8];
    const u64 L2E  = pk(1.44269504f, 1.44269504f);
    const u64 NEG1 = pk(-1.f, -1.f);
    #pragma unroll
    for (int p = 0; p < 8; ++p) acc2[p] = 0ull;
    float smA = 0.f;

    __syncthreads();

    u64 e2A[8], e2B[8];
    float sumA, ssqA, sumB, ssqB;

    #define LN_STAGE(EE, SUM, SSQ, JJ) {                                      \
        const ulonglong2* vr = (const ulonglong2*)(sv + (JJ) * 256);          \
        {                                                                     \
            const ulonglong2 q0 = vr[sub];                                    \
            const ulonglong2 q1 = vr[16 + sub];                               \
            const ulonglong2 q2 = vr[32 + sub];                               \
            const ulonglong2 q3 = vr[48 + sub];                               \
            EE[0] = elu2(ru2[0], q0.x, L2E, NEG1);                            \
            EE[1] = elu2(ru2[1], q0.y, L2E, NEG1);                            \
            EE[2] = elu2(ru2[2], q1.x, L2E, NEG1);                            \
            EE[3] = elu2(ru2[3], q1.y, L2E, NEG1);                            \
            EE[4] = elu2(ru2[4], q2.x, L2E, NEG1);                            \
            EE[5] = elu2(ru2[5], q2.y, L2E, NEG1);                            \
            EE[6] = elu2(ru2[6], q3.x, L2E, NEG1);                            \
            EE[7] = elu2(ru2[7], q3.y, L2E, NEG1);                            \
        }                                                                     \
        u64 se = add2(add2(add2(EE[0], EE[1]), add2(EE[2], EE[3])),           \
                      add2(add2(EE[4], EE[5]), add2(EE[6], EE[7])));          \
        u64 sq = mul2(EE[0], EE[0]);                                          \
        sq = fma2(EE[1], EE[1], sq); sq = fma2(EE[2], EE[2], sq);             \
        sq = fma2(EE[3], EE[3], sq); sq = fma2(EE[4], EE[4], sq);             \
        sq = fma2(EE[5], EE[5], sq); sq = fma2(EE[6], EE[6], sq);             \
        sq = fma2(EE[7], EE[7], sq);                                          \
        float selo, sehi, sqlo, sqhi;                                         \
        upk(se, selo, sehi); upk(sq, sqlo, sqhi);                             \
        SUM = selo + sehi; SSQ = sqlo + sqhi; }

    #pragma unroll 2
    for (int sI = 0; sI < 32; sI += 2) {
        LN_STAGE(e2A, sumA, ssqA, 2 * sI + half);
        LN_STAGE(e2B, sumB, ssqB, 2 * (sI + 1) + half);

        #pragma unroll
        for (int o = 8; o; o >>= 1) {
            sumA += __shfl_xor_sync(~0u, sumA, o);
            sumB += __shfl_xor_sync(~0u, sumB, o);
            ssqA += __shfl_xor_sync(~0u, ssqA, o);
            ssqB += __shfl_xor_sync(~0u, ssqB, o);
        }
        const float meanA = sumA * (1.f / H);
        const float meanB = sumB * (1.f / H);
        const float varA  = fmaf(ssqA, 1.f / H, -meanA * meanA);
        const float varB  = fmaf(ssqB, 1.f / H, -meanB * meanB);
        const float AA    = rsqrtf(varA + 1e-5f);
        const float AB    = rsqrtf(varB + 1e-5f);
        smA = fmaf(meanA, AA, smA);
        smA = fmaf(meanB, AB, smA);
        const u64 AA2 = pk(AA, AA);
        const u64 AB2 = pk(AB, AB);
        #pragma unroll
        for (int p = 0; p < 8; ++p) {
            acc2[p] = fma2(e2A[p], AA2, acc2[p]);
            acc2[p] = fma2(e2B[p], AB2, acc2[p]);
        }
    }
    #undef LN_STAGE

    #pragma unroll
    for (int p = 0; p < 8; ++p) acc2[p] = add2(acc2[p], shfl_xor_u64(acc2[p], 16));
    smA += __shfl_xor_sync(~0u, smA, 16);

    __syncthreads();                       // all warps done reading sv
    if (half == 0) {
        const u64 nsmA = pk(-smA, -smA);
        u64* dst = (u64*)&sv[w * H + ch0];
        #pragma unroll
        for (int p = 0; p < 8; ++p) dst[p] = add2(acc2[p], nsmA);
    }
    __syncthreads();
    if (tid < H) {
        float s = 0.f;
        #pragma unroll
        for (int ww = 0; ww < 16; ++ww) s += sv[ww * H + tid];
        // block covers 16 i * 64 j = 1024 pairs -> 1024 * beta
        g_p[bid * H + tid] = fmaf(lg[tid], s, 1024.f * lb[tid]);
    }

    // ---- fused finale: last block for b does the final reduce + W_f GEMM ----
    __syncthreads();
    __threadfence();                       // publish g_p row (writers tid<H)
    __syncthreads();
    if (tid == 0) s_flag = atomicAdd(&g_cnt[b], 1);
    __syncthreads();
    if (s_flag == 3) {
        __threadfence();                   // acquire side
        float* ss   = sv;                  // reuse smem
        float* part = sv + H;
        if (tid < H) {
            float s = 0.f;
            #pragma unroll
            for (int ig = 0; ig < 4; ++ig)
                s += __ldcg(&g_p[(b * 4 + ig) * H + tid]);   // L2 reads (bypass L1)
            ss[tid] = s;
        }
        __syncthreads();

        const int f   = tid & (F - 1);
        const int seg = tid >> 7;          // 0..3
        const int hb  = seg * 64;
        float a0 = 0.f, a1 = 0.f, a2 = 0.f, a3 = 0.f;
        #pragma unroll 4
        for (int hh = 0; hh < 64; hh += 4) {
            a0 = fmaf(ss[hb + hh + 0], Wf[(hb + hh + 0) * F + f], a0);
            a1 = fmaf(ss[hb + hh + 1], Wf[(hb + hh + 1) * F + f], a1);
            a2 = fmaf(ss[hb + hh + 2], Wf[(hb + hh + 2) * F + f], a2);
            a3 = fmaf(ss[hb + hh + 3], Wf[(hb + hh + 3) * F + f], a3);
        }
        const float r = (a0 + a1) + (a2 + a3);
        if (seg) part[(seg - 1) * F + f] = r;
        __syncthreads();
        if (seg == 0) {
            const float o = bf[f] + r + part[f] + part[F + f] + part[2 * F + f];
            out[b * F + f] = (o > 0.f) ? o : expm1f(o);
        }
        if (tid == 0) g_cnt[b] = 0;        // reset for next graph replay
    }
}

// ---------------------------------------------------------------------------
extern "C" void kernel_launch(void* const* d_in, const int* in_sizes, int n_in,
                              void* d_out, int out_size)
{
    const float* x_a   = (const float*)d_in[0];
    const float* x_b   = (const float*)d_in[1];
    const float* W_a   = (const float*)d_in[2];
    const float* b_a   = (const float*)d_in[3];
    const float* W_b   = (const float*)d_in[4];
    const float* b_b   = (const float*)d_in[5];
    const float* ln0_g = (const float*)d_in[6];
    const float* ln0_b = (const float*)d_in[7];
    const float* W_g   = (const float*)d_in[8];
    const float* b_g   = (const float*)d_in[9];
    const float* lng_g = (const float*)d_in[10];
    const float* lng_b = (const float*)d_in[11];
    const float* W_f   = (const float*)d_in[12];
    const float* b_f   = (const float*)d_in[13];
    float* out = (float*)d_out;

    k_embed_ln<<<B, 256>>>(x_a, x_b, W_a, b_a, W_b, b_b, ln0_g, ln0_b);

    k_uv<<<B * NN / 32, 256>>>(W_g, b_g);

    const size_t smem_p = NN * H * sizeof(float);   // 64 KB
    cudaFuncSetAttribute(k_pair, cudaFuncAttributeMaxDynamicSharedMemorySize, (int)smem_p);
    k_pair<<<B * 4, 512, smem_p>>>(lng_g, lng_b, W_f, b_f, out);
}

// round 17
// speedup vs baseline: 1.0918x; 1.0918x over previous
#include <cuda_runtime.h>
#include <cuda_bf16.h>

#define B    128
#define N1   32
#define N2   32
#define D1   23
#define D2   13
#define NN   64
#define E    72
#define H    256
#define F    128
#define LNCNT 4608

typedef unsigned long long u64;

// ---- f32x2 packed helpers (sm_103a) ----
__device__ __forceinline__ u64 pk(float lo, float hi) {
    u64 r; asm("mov.b64 %0, {%1,%2};" : "=l"(r) : "f"(lo), "f"(hi)); return r;
}
__device__ __forceinline__ void upk(u64 x, float& lo, float& hi) {
    asm("mov.b64 {%0,%1}, %2;" : "=f"(lo), "=f"(hi) : "l"(x));
}
__device__ __forceinline__ u64 add2(u64 a, u64 b) {
    u64 d; asm("add.rn.f32x2 %0,%1,%2;" : "=l"(d) : "l"(a), "l"(b)); return d;
}
__device__ __forceinline__ u64 mul2(u64 a, u64 b) {
    u64 d; asm("mul.rn.f32x2 %0,%1,%2;" : "=l"(d) : "l"(a), "l"(b)); return d;
}
__device__ __forceinline__ u64 fma2(u64 a, u64 b, u64 c) {
    u64 d; asm("fma.rn.f32x2 %0,%1,%2,%3;" : "=l"(d) : "l"(a), "l"(b), "l"(c)); return d;
}
__device__ __forceinline__ u64 shfl_xor_u64(u64 x, int o) {
    float lo, hi; upk(x, lo, hi);
    lo = __shfl_xor_sync(~0u, lo, o);
    hi = __shfl_xor_sync(~0u, hi, o);
    return pk(lo, hi);
}

// Fused packed ELU: e = min(max(t,0), e^t - 1), t = u + v.
__device__ __forceinline__ u64 elu2(u64 u2, u64 v2, u64 l2e, u64 neg1) {
    u64 e;
    asm("{\n\t"
        ".reg .b64 t2, x2, em2;\n\t"
        ".reg .f32 t0, t1, x0, x1, m0, m1, r0, r1;\n\t"
        "add.rn.f32x2 t2, %1, %2;\n\t"
        "mul.rn.f32x2 x2, t2, %3;\n\t"
        "mov.b64 {x0,x1}, x2;\n\t"
        "ex2.approx.ftz.f32 x0, x0;\n\t"
        "ex2.approx.ftz.f32 x1, x1;\n\t"
        "mov.b64 x2, {x0,x1};\n\t"
        "add.rn.f32x2 em2, x2, %4;\n\t"
        "mov.b64 {m0,m1}, em2;\n\t"
        "mov.b64 {t0,t1}, t2;\n\t"
        "max.f32 r0, t0, 0f00000000;\n\t"
        "max.f32 r1, t1, 0f00000000;\n\t"
        "min.f32 r0, r0, m0;\n\t"
        "min.f32 r1, r1, m1;\n\t"
        "mov.b64 %0, {r0,r1};\n\t"
        "}" : "=l"(e) : "l"(u2), "l"(v2), "l"(l2e), "l"(neg1));
    return e;
}

// Scratch
__device__ float g_a[B * NN * E];
__device__ float g_u[B * NN * H];
__device__ float g_v[B * NN * H];
__device__ float g_p[B * 4 * H];

// ---------------------------------------------------------------------------
// K1: split-embedding + joint LayerNorm. One block per b, 1024 THREADS:
// 32 warps = 8/SMSP for latency cover (the 256-thr version measured 21.4us
// at occ 12.5% — pure latency starvation on a 42M-FMA job).
// Each thread handles 4-5 of the 4608 (n,e) elements.
// ---------------------------------------------------------------------------
__global__ __launch_bounds__(1024) void k_embed_ln(
    const float* __restrict__ xa, const float* __restrict__ xb,
    const float* __restrict__ Wa, const float* __restrict__ ba,
    const float* __restrict__ Wb, const float* __restrict__ bb,
    const float* __restrict__ g0, const float* __restrict__ b0)
{
    const int b   = blockIdx.x;
    const int tid = threadIdx.x;
    __shared__ float sWa[D1 * E];
    __shared__ float sWb[D2 * E];
    __shared__ float sba[E], sbb[E];
    __shared__ float rsum[32], rssq[32];
    __shared__ float s_mean, s_rstd;

    for (int i = tid; i < D1 * E; i += 1024) sWa[i] = Wa[i];
    for (int i = tid; i < D2 * E; i += 1024) sWb[i] = Wb[i];
    if (tid < E) { sba[tid] = ba[tid]; sbb[tid] = bb[tid]; }
    __syncthreads();

    float vals[5];
    float sum = 0.f, ssq = 0.f;

    #pragma unroll
    for (int c = 0; c < 5; ++c) {
        const int idx = tid + c * 1024;
        if (idx < LNCNT) {
            const int n = idx / E;
            const int e = idx - n * E;
            float acc;
            if (n < N1) {
                acc = sba[e];
                const float* xr = xa + (b * N1 + n) * D1;
                #pragma unroll
                for (int k = 0; k < D1; ++k) acc = fmaf(xr[k], sWa[k * E + e], acc);
            } else {
                acc = sbb[e];
                const float* xr = xb + (b * N2 + (n - N1)) * D2;
                #pragma unroll
                for (int k = 0; k < D2; ++k) acc = fmaf(xr[k], sWb[k * E + e], acc);
            }
            vals[c] = acc;
            sum += acc;
            ssq = fmaf(acc, acc, ssq);
        }
    }

    #pragma unroll
    for (int o = 16; o; o >>= 1) {
        sum += __shfl_xor_sync(~0u, sum, o);
        ssq += __shfl_xor_sync(~0u, ssq, o);
    }
    const int w = tid >> 5, lane = tid & 31;
    if (lane == 0) { rsum[w] = sum; rssq[w] = ssq; }
    __syncthreads();
    if (w == 0) {
        float s = (lane < 32) ? rsum[lane] : 0.f;
        float q = (lane < 32) ? rssq[lane] : 0.f;
        #pragma unroll
        for (int o = 16; o; o >>= 1) {
            s += __shfl_xor_sync(~0u, s, o);
            q += __shfl_xor_sync(~0u, q, o);
        }
        if (lane == 0) {
            const float mean = s * (1.f / LNCNT);
            const float var  = fmaf(q, 1.f / LNCNT, -mean * mean);
            s_mean = mean;
            s_rstd = rsqrtf(var + 1e-5f);
        }
    }
    __syncthreads();
    const float mean = s_mean, rstd = s_rstd;

    #pragma unroll
    for (int c = 0; c < 5; ++c) {
        const int idx = tid + c * 1024;
        if (idx < LNCNT)
            g_a[b * LNCNT + idx] = (vals[c] - mean) * rstd * g0[idx] + b0[idx];
    }
}

// ---------------------------------------------------------------------------
// K2: u = a @ Wg[0:72] + b_g ; v = a @ Wg[72:144].
// 16 rows/block, global Wg (L2-resident, MLP~16). Grid = 512.  (R15 form.)
// ---------------------------------------------------------------------------
__global__ __launch_bounds__(256) void k_uv(
    const float* __restrict__ Wg, const float* __restrict__ bg)
{
    __shared__ float sa[E * 16];
    const int m0 = blockIdx.x * 16;
    const int h  = threadIdx.x;

    for (int idx = h; idx < E * 16; idx += 256) {
        const int rr = idx / E, k = idx - rr * E;
        sa[k * 16 + rr] = g_a[(m0 + rr) * E + k];
    }
    __syncthreads();

    const float bgh = bg[h];
    u64 uacc[8], vacc[8];
    const u64 bg2 = pk(bgh, bgh);
    #pragma unroll
    for (int p = 0; p < 8; ++p) { uacc[p] = bg2; vacc[p] = 0ull; }

    #pragma unroll 8
    for (int k = 0; k < E; ++k) {
        const ulonglong2* ar = (const ulonglong2*)&sa[k * 16];
        const ulonglong2 q0 = ar[0], q1 = ar[1], q2 = ar[2], q3 = ar[3];
        const u64 av[8] = {q0.x, q0.y, q1.x, q1.y, q2.x, q2.y, q3.x, q3.y};
        const float w0 = Wg[k * H + h];
        const float w1 = Wg[(E + k) * H + h];
        const u64 w02 = pk(w0, w0);
        const u64 w12 = pk(w1, w1);
        #pragma unroll
        for (int p = 0; p < 8; ++p) {
            uacc[p] = fma2(av[p], w02, uacc[p]);
            vacc[p] = fma2(av[p], w12, vacc[p]);
        }
    }

    #pragma unroll
    for (int p = 0; p < 8; ++p) {
        float lo, hi;
        upk(uacc[p], lo, hi);
        g_u[(m0 + 2 * p) * H + h]     = lo;
        g_u[(m0 + 2 * p + 1) * H + h] = hi;
        upk(vacc[p], lo, hi);
        g_v[(m0 + 2 * p) * H + h]     = lo;
        g_v[(m0 + 2 * p + 1) * H + h] = hi;
    }
}

// ---------------------------------------------------------------------------
// K3: pairwise Σ_j LN_H(ELU(u_i + v_j)). 512-thread form (measured ~45us):
// 16 i's share one v[b] staging; R5-verbatim inner loop.
// Block = (b, iq). Grid = 512.
// ---------------------------------------------------------------------------
__global__ __launch_bounds__(512) void k_pair(
    const float* __restrict__ lg, const float* __restrict__ lb)
{
    extern __shared__ float sv[];               // [64][256] swizzled v[b]
    const int bid  = blockIdx.x;
    const int b    = bid >> 2;
    const int iq   = bid & 3;
    const int tid  = threadIdx.x;
    const int w    = tid >> 5;                  // 0..15
    const int lane = tid & 31;
    const int half = lane >> 4;
    const int sub  = lane & 15;
    const int ch0  = sub * 16;

    {
        const float4* vb = (const float4*)(g_v + b * NN * H);
        float4* s4 = (float4*)sv;
        #pragma unroll
        for (int c = 0; c < 8; ++c) {
            const int g = tid + c * 512;        // < 4096
            const int j = g >> 6;
            const int q = g & 63;
            s4[j * 64 + (q & 3) * 16 + (q >> 2)] = vb[g];
        }
    }

    const int m = b * NN + iq * 16 + w;

    u64 ru2[8];
    {
        const ulonglong2* uu = (const ulonglong2*)(g_u + m * H + ch0);
        const ulonglong2 a0 = uu[0], a1 = uu[1], a2 = uu[2], a3 = uu[3];
        ru2[0] = a0.x; ru2[1] = a0.y; ru2[2] = a1.x; ru2[3] = a1.y;
        ru2[4] = a2.x; ru2[5] = a2.y; ru2[6] = a3.x; ru2[7] = a3.y;
    }
    u64 acc2[8];
    const u64 L2E  = pk(1.44269504f, 1.44269504f);
    const u64 NEG1 = pk(-1.f, -1.f);
    #pragma unroll
    for (int p = 0; p < 8; ++p) acc2[p] = 0ull;
    float smA = 0.f;

    __syncthreads();

    u64 e2A[8], e2B[8];
    float sumA, ssqA, sumB, ssqB;

    #define LN_STAGE(EE, SUM, SSQ, JJ) {                                      \
        const ulonglong2* vr = (const ulonglong2*)(sv + (JJ) * 256);          \
        {                                                                     \
            const ulonglong2 q0 = vr[sub];                                    \
            const ulonglong2 q1 = vr[16 + sub];                               \
            const ulonglong2 q2 = vr[32 + sub];                               \
            const ulonglong2 q3 = vr[48 + sub];                               \
            EE[0] = elu2(ru2[0], q0.x, L2E, NEG1);                            \
            EE[1] = elu2(ru2[1], q0.y, L2E, NEG1);                            \
            EE[2] = elu2(ru2[2], q1.x, L2E, NEG1);                            \
            EE[3] = elu2(ru2[3], q1.y, L2E, NEG1);                            \
            EE[4] = elu2(ru2[4], q2.x, L2E, NEG1);                            \
            EE[5] = elu2(ru2[5], q2.y, L2E, NEG1);                            \
            EE[6] = elu2(ru2[6], q3.x, L2E, NEG1);                            \
            EE[7] = elu2(ru2[7], q3.y, L2E, NEG1);                            \
        }                                                                     \
        u64 se = add2(add2(add2(EE[0], EE[1]), add2(EE[2], EE[3])),           \
                      add2(add2(EE[4], EE[5]), add2(EE[6], EE[7])));          \
        u64 sq = mul2(EE[0], EE[0]);                                          \
        sq = fma2(EE[1], EE[1], sq); sq = fma2(EE[2], EE[2], sq);             \
        sq = fma2(EE[3], EE[3], sq); sq = fma2(EE[4], EE[4], sq);             \
        sq = fma2(EE[5], EE[5], sq); sq = fma2(EE[6], EE[6], sq);             \
        sq = fma2(EE[7], EE[7], sq);                                          \
        float selo, sehi, sqlo, sqhi;                                         \
        upk(se, selo, sehi); upk(sq, sqlo, sqhi);                             \
        SUM = selo + sehi; SSQ = sqlo + sqhi; }

    #pragma unroll 2
    for (int sI = 0; sI < 32; sI += 2) {
        LN_STAGE(e2A, sumA, ssqA, 2 * sI + half);
        LN_STAGE(e2B, sumB, ssqB, 2 * (sI + 1) + half);

        #pragma unroll
        for (int o = 8; o; o >>= 1) {
            sumA += __shfl_xor_sync(~0u, sumA, o);
            sumB += __shfl_xor_sync(~0u, sumB, o);
            ssqA += __shfl_xor_sync(~0u, ssqA, o);
            ssqB += __shfl_xor_sync(~0u, ssqB, o);
        }
        const float meanA = sumA * (1.f / H);
        const float meanB = sumB * (1.f / H);
        const float varA  = fmaf(ssqA, 1.f / H, -meanA * meanA);
        const float varB  = fmaf(ssqB, 1.f / H, -meanB * meanB);
        const float AA    = rsqrtf(varA + 1e-5f);
        const float AB    = rsqrtf(varB + 1e-5f);
        smA = fmaf(meanA, AA, smA);
        smA = fmaf(meanB, AB, smA);
        const u64 AA2 = pk(AA, AA);
        const u64 AB2 = pk(AB, AB);
        #pragma unroll
        for (int p = 0; p < 8; ++p) {
            acc2[p] = fma2(e2A[p], AA2, acc2[p]);
            acc2[p] = fma2(e2B[p], AB2, acc2[p]);
        }
    }
    #undef LN_STAGE

    #pragma unroll
    for (int p = 0; p < 8; ++p) acc2[p] = add2(acc2[p], shfl_xor_u64(acc2[p], 16));
    smA += __shfl_xor_sync(~0u, smA, 16);

    __syncthreads();                       // all warps done reading sv
    if (half == 0) {
        const u64 nsmA = pk(-smA, -smA);
        u64* dst = (u64*)&sv[w * H + ch0];
        #pragma unroll
        for (int p = 0; p < 8; ++p) dst[p] = add2(acc2[p], nsmA);
    }
    __syncthreads();
    if (tid < H) {
        float s = 0.f;
        #pragma unroll
        for (int ww = 0; ww < 16; ++ww) s += sv[ww * H + tid];
        // block covers 16 i * 64 j = 1024 pairs -> 1024 * beta
        g_p[bid * H + tid] = fmaf(lg[tid], s, 1024.f * lb[tid]);
    }
}

// ---------------------------------------------------------------------------
// K4: s[b] = Σ 4 partials; out = ELU(s @ W_f + b_f).
// 4-way F-split: 512 blocks, 256 thr.
// ---------------------------------------------------------------------------
__global__ __launch_bounds__(256) void k_final(
    const float* __restrict__ Wf, const float* __restrict__ bf,
    float* __restrict__ out)
{
    const int bid  = blockIdx.x;
    const int b    = bid >> 2;
    const int fq   = bid & 3;
    const int tid  = threadIdx.x;
    const int w    = tid >> 5;
    const int lane = tid & 31;
    __shared__ float ss[H];
    __shared__ float part[8][32];

    {
        float s = 0.f;
        #pragma unroll
        for (int ig = 0; ig < 4; ++ig) s += g_p[(b * 4 + ig) * H + tid];
        ss[tid] = s;
    }
    __syncthreads();

    const int f  = fq * 32 + lane;
    const int h0 = w * 32;
    float a0 = 0.f, a1 = 0.f, a2 = 0.f, a3 = 0.f;
    #pragma unroll
    for (int hh = 0; hh < 32; hh += 4) {
        a0 = fmaf(ss[h0 + hh + 0], Wf[(h0 + hh + 0) * F + f], a0);
        a1 = fmaf(ss[h0 + hh + 1], Wf[(h0 + hh + 1) * F + f], a1);
        a2 = fmaf(ss[h0 + hh + 2], Wf[(h0 + hh + 2) * F + f], a2);
        a3 = fmaf(ss[h0 + hh + 3], Wf[(h0 + hh + 3) * F + f], a3);
    }
    part[w][lane] = (a0 + a1) + (a2 + a3);
    __syncthreads();

    if (w == 0) {
        float o = bf[f];
        #pragma unroll
        for (int k = 0; k < 8; ++k) o += part[k][lane];
        out[b * F + f] = (o > 0.f) ? o : expm1f(o);
    }
}

// ---------------------------------------------------------------------------
extern "C" void kernel_launch(void* const* d_in, const int* in_sizes, int n_in,
                              void* d_out, int out_size)
{
    const float* x_a   = (const float*)d_in[0];
    const float* x_b   = (const float*)d_in[1];
    const float* W_a   = (const float*)d_in[2];
    const float* b_a   = (const float*)d_in[3];
    const float* W_b   = (const float*)d_in[4];
    const float* b_b   = (const float*)d_in[5];
    const float* ln0_g = (const float*)d_in[6];
    const float* ln0_b = (const float*)d_in[7];
    const float* W_g   = (const float*)d_in[8];
    const float* b_g   = (const float*)d_in[9];
    const float* lng_g = (const float*)d_in[10];
    const float* lng_b = (const float*)d_in[11];
    const float* W_f   = (const float*)d_in[12];
    const float* b_f   = (const float*)d_in[13];
    float* out = (float*)d_out;

    k_embed_ln<<<B, 1024>>>(x_a, x_b, W_a, b_a, W_b, b_b, ln0_g, ln0_b);

    k_uv<<<B * NN / 16, 256>>>(W_g, b_g);

    const size_t smem_p = NN * H * sizeof(float);   // 64 KB
    cudaFuncSetAttribute(k_pair, cudaFuncAttributeMaxDynamicSharedMemorySize, (int)smem_p);
    k_pair<<<B * 4, 512, smem_p>>>(lng_g, lng_b);

    k_final<<<B * 4, 256>>>(W_f, b_f, out);
}